// round 2
// baseline (speedup 1.0000x reference)
#include <cuda_runtime.h>
#include <math.h>

// ---------------- problem constants ----------------
#define T_TOK 4096       // B*S tokens
#define HID   2048       // hidden size
#define NEXP  8          // experts
#define IDIM  1024       // expert intermediate
#define RROWS 8192       // routed rows = T_TOK * top_k (always exact)
#define SROWS 4096       // shared-expert rows
#define NROWS 12288      // RROWS + SROWS
#define MAXTILES 128     // >= sum ceil(n_e/128) (<=71) + 32 shared tiles

// ---------------- static device scratch (no cudaMalloc allowed) ----------------
__device__ float g_buf[(size_t)NROWS * IDIM];   // gate pre-act, then h = silu(g)*u
__device__ float u_buf[(size_t)NROWS * IDIM];   // up pre-act
__device__ float y_buf[(size_t)RROWS * HID];    // routed expert down-proj outputs
__device__ int   topk_idx_d[T_TOK * 2];
__device__ float topk_w_d[T_TOK * 2];
__device__ int   tok_d[NROWS];                  // row -> token id
__device__ int   row_of_d[T_TOK * 2];           // (token,slot) -> routed row (inverse map)
__device__ int   tile_grp_d[MAXTILES];
__device__ int   tile_row0_d[MAXTILES];
__device__ int   tile_rows_d[MAXTILES];
__device__ int   n_tiles_d;
__device__ int   grp_off_d[NEXP + 1];

// ---------------- router: logits + top-2 (raw logits are combine weights) ----------------
__global__ __launch_bounds__(256) void router_kernel(const float* __restrict__ x,
                                                     const float* __restrict__ rw) {
    __shared__ float sx[HID];
    __shared__ float slog[NEXP];
    const int t = blockIdx.x;
    const float* xr = x + (size_t)t * HID;
    for (int i = threadIdx.x; i < HID / 4; i += 256)
        ((float4*)sx)[i] = ((const float4*)xr)[i];
    __syncthreads();
    const int w = threadIdx.x >> 5, lane = threadIdx.x & 31;  // 8 warps = 8 experts
    const float* re = rw + (size_t)w * HID;
    float s = 0.f;
    for (int k = lane; k < HID; k += 32) s += sx[k] * re[k];
    #pragma unroll
    for (int o = 16; o; o >>= 1) s += __shfl_down_sync(0xffffffffu, s, o);
    if (lane == 0) slog[w] = s;
    __syncthreads();
    if (threadIdx.x == 0) {
        float b = -3.4e38f; int bi = 0;
        #pragma unroll
        for (int e = 0; e < NEXP; e++) if (slog[e] > b) { b = slog[e]; bi = e; }
        float b2 = -3.4e38f; int si = 0;
        #pragma unroll
        for (int e = 0; e < NEXP; e++) if (e != bi && slog[e] > b2) { b2 = slog[e]; si = e; }
        topk_idx_d[2 * t] = bi;      topk_w_d[2 * t] = b;
        topk_idx_d[2 * t + 1] = si;  topk_w_d[2 * t + 1] = b2;
    }
}

// ---------------- deterministic list build: stable compaction per expert ----------------
__global__ void build_kernel() {
    __shared__ int sscan[256];
    __shared__ int sbase, sebase;
    const int tid = threadIdx.x;
    if (tid == 0) { sebase = 0; grp_off_d[0] = 0; }
    __syncthreads();
    for (int e = 0; e < NEXP; e++) {
        if (tid == 0) sbase = 0;
        __syncthreads();
        for (int c = 0; c < T_TOK; c += 256) {
            const int t = c + tid;
            int slot = -1;
            if (topk_idx_d[2 * t] == e) slot = 0;
            else if (topk_idx_d[2 * t + 1] == e) slot = 1;
            const int f = (slot >= 0) ? 1 : 0;
            sscan[tid] = f;
            __syncthreads();
            #pragma unroll
            for (int o = 1; o < 256; o <<= 1) {
                int v = (tid >= o) ? sscan[tid - o] : 0;
                __syncthreads();
                sscan[tid] += v;
                __syncthreads();
            }
            if (f) {
                const int pos = sebase + sbase + sscan[tid] - 1;
                tok_d[pos] = t;
                row_of_d[2 * t + slot] = pos;
            }
            const int tot = sscan[255];
            __syncthreads();
            if (tid == 0) sbase += tot;
            __syncthreads();
        }
        if (tid == 0) { sebase += sbase; grp_off_d[e + 1] = sebase; }
        __syncthreads();
    }
    // shared-expert pseudo-group covers all tokens
    for (int i = tid; i < SROWS; i += 256) tok_d[RROWS + i] = i;
    __syncthreads();
    if (tid == 0) {
        int nt = 0;
        for (int g = 0; g < NEXP; g++) {
            const int r0 = grp_off_d[g], r1 = grp_off_d[g + 1];
            for (int r = r0; r < r1; r += 128) {
                tile_grp_d[nt] = g; tile_row0_d[nt] = r;
                tile_rows_d[nt] = min(128, r1 - r); nt++;
            }
        }
        for (int r = RROWS; r < NROWS; r += 128) {
            tile_grp_d[nt] = NEXP; tile_row0_d[nt] = r; tile_rows_d[nt] = 128; nt++;
        }
        n_tiles_d = nt;
    }
}

// ---------------- up/gate grouped GEMM: C = gather(X) @ B ----------------
// blockIdx.z: 0 -> gate weights into g_buf, 1 -> up weights into u_buf.
__global__ __launch_bounds__(256) void up_gemm_kernel(
    const float* __restrict__ x,
    const float* __restrict__ wg, const float* __restrict__ wu,
    const float* __restrict__ sgw, const float* __restrict__ suw,
    const float* __restrict__ sgb, const float* __restrict__ sub) {
    const int tile = blockIdx.x;
    if (tile >= n_tiles_d) return;
    const int g = tile_grp_d[tile];
    const int row0 = tile_row0_d[tile];
    const int rows = tile_rows_d[tile];
    const int z = blockIdx.z;
    const float* B;
    const float* bias = nullptr;
    if (g < NEXP) B = (z ? wu : wg) + (size_t)g * HID * IDIM;
    else { B = z ? suw : sgw; bias = z ? sub : sgb; }
    float* C = z ? u_buf : g_buf;
    const int n0 = blockIdx.y * 128;

    __shared__ float As[16][128];
    __shared__ float Bs[16][128];

    const int tid = threadIdx.x;
    const int tx = tid & 15, ty = tid >> 4;
    const int am = tid & 127;
    const int ak = (tid >> 7) * 8;
    const int tok = tok_d[row0 + am];           // row0+127 < NROWS always
    const float* aptr = x + (size_t)tok * HID + ak;
    const int bn = (tid & 31) * 4;
    const int bk = tid >> 5;

    float acc[8][8];
    #pragma unroll
    for (int i = 0; i < 8; i++)
        #pragma unroll
        for (int j = 0; j < 8; j++) acc[i][j] = 0.f;

    for (int k0 = 0; k0 < HID; k0 += 16) {
        float4 a0 = *(const float4*)(aptr + k0);
        float4 a1 = *(const float4*)(aptr + k0 + 4);
        As[ak + 0][am] = a0.x; As[ak + 1][am] = a0.y;
        As[ak + 2][am] = a0.z; As[ak + 3][am] = a0.w;
        As[ak + 4][am] = a1.x; As[ak + 5][am] = a1.y;
        As[ak + 6][am] = a1.z; As[ak + 7][am] = a1.w;
        const float* bp = B + (size_t)(k0 + bk) * IDIM + n0 + bn;
        *(float4*)&Bs[bk][bn]     = *(const float4*)bp;
        *(float4*)&Bs[bk + 8][bn] = *(const float4*)(bp + 8 * IDIM);
        __syncthreads();
        #pragma unroll
        for (int k = 0; k < 16; k++) {
            float a[8], b[8];
            *(float4*)(a)     = *(float4*)&As[k][ty * 8];
            *(float4*)(a + 4) = *(float4*)&As[k][ty * 8 + 4];
            *(float4*)(b)     = *(float4*)&Bs[k][tx * 8];
            *(float4*)(b + 4) = *(float4*)&Bs[k][tx * 8 + 4];
            #pragma unroll
            for (int i = 0; i < 8; i++)
                #pragma unroll
                for (int j = 0; j < 8; j++) acc[i][j] += a[i] * b[j];
        }
        __syncthreads();
    }
    #pragma unroll
    for (int i = 0; i < 8; i++) {
        const int m = ty * 8 + i;
        if (m < rows) {
            float* cp = C + (size_t)(row0 + m) * IDIM + n0 + tx * 8;
            #pragma unroll
            for (int j = 0; j < 8; j += 4) {
                float4 v;
                v.x = acc[i][j]; v.y = acc[i][j + 1]; v.z = acc[i][j + 2]; v.w = acc[i][j + 3];
                if (bias) {
                    const int c = n0 + tx * 8 + j;
                    v.x += bias[c]; v.y += bias[c + 1]; v.z += bias[c + 2]; v.w += bias[c + 3];
                }
                *(float4*)(cp + j) = v;
            }
        }
    }
}

// ---------------- h = silu(g) * u, in place into g_buf ----------------
__global__ void act_kernel() {
    const size_t i = (size_t)blockIdx.x * 256 + threadIdx.x;
    if (i >= (size_t)NROWS * IDIM / 4) return;
    float4 gv = ((const float4*)g_buf)[i];
    float4 uv = ((const float4*)u_buf)[i];
    gv.x = gv.x / (1.f + expf(-gv.x)) * uv.x;
    gv.y = gv.y / (1.f + expf(-gv.y)) * uv.y;
    gv.z = gv.z / (1.f + expf(-gv.z)) * uv.z;
    gv.w = gv.w / (1.f + expf(-gv.w)) * uv.w;
    ((float4*)g_buf)[i] = gv;
}

// ---------------- down grouped GEMM: routed -> y_buf, shared -> out (+bias) ----------------
__global__ __launch_bounds__(256) void down_gemm_kernel(
    const float* __restrict__ wd, const float* __restrict__ sdw,
    const float* __restrict__ sdb, float* __restrict__ out) {
    const int tile = blockIdx.x;
    if (tile >= n_tiles_d) return;
    const int g = tile_grp_d[tile];
    const int row0 = tile_row0_d[tile];
    const int rows = tile_rows_d[tile];
    const float* B = (g < NEXP) ? wd + (size_t)g * IDIM * HID : sdw;
    const int n0 = blockIdx.y * 128;

    __shared__ float As[16][128];
    __shared__ float Bs[16][128];

    const int tid = threadIdx.x;
    const int tx = tid & 15, ty = tid >> 4;
    const int am = tid & 127;
    const int ak = (tid >> 7) * 8;
    const float* aptr = g_buf + (size_t)(row0 + am) * IDIM + ak;
    const int bn = (tid & 31) * 4;
    const int bk = tid >> 5;

    float acc[8][8];
    #pragma unroll
    for (int i = 0; i < 8; i++)
        #pragma unroll
        for (int j = 0; j < 8; j++) acc[i][j] = 0.f;

    for (int k0 = 0; k0 < IDIM; k0 += 16) {
        float4 a0 = *(const float4*)(aptr + k0);
        float4 a1 = *(const float4*)(aptr + k0 + 4);
        As[ak + 0][am] = a0.x; As[ak + 1][am] = a0.y;
        As[ak + 2][am] = a0.z; As[ak + 3][am] = a0.w;
        As[ak + 4][am] = a1.x; As[ak + 5][am] = a1.y;
        As[ak + 6][am] = a1.z; As[ak + 7][am] = a1.w;
        const float* bp = B + (size_t)(k0 + bk) * HID + n0 + bn;
        *(float4*)&Bs[bk][bn]     = *(const float4*)bp;
        *(float4*)&Bs[bk + 8][bn] = *(const float4*)(bp + 8 * HID);
        __syncthreads();
        #pragma unroll
        for (int k = 0; k < 16; k++) {
            float a[8], b[8];
            *(float4*)(a)     = *(float4*)&As[k][ty * 8];
            *(float4*)(a + 4) = *(float4*)&As[k][ty * 8 + 4];
            *(float4*)(b)     = *(float4*)&Bs[k][tx * 8];
            *(float4*)(b + 4) = *(float4*)&Bs[k][tx * 8 + 4];
            #pragma unroll
            for (int i = 0; i < 8; i++)
                #pragma unroll
                for (int j = 0; j < 8; j++) acc[i][j] += a[i] * b[j];
        }
        __syncthreads();
    }
    #pragma unroll
    for (int i = 0; i < 8; i++) {
        const int m = ty * 8 + i;
        if (m < rows) {
            if (g < NEXP) {
                float* yp = y_buf + (size_t)(row0 + m) * HID + n0 + tx * 8;
                #pragma unroll
                for (int j = 0; j < 8; j += 4) {
                    float4 v;
                    v.x = acc[i][j]; v.y = acc[i][j + 1]; v.z = acc[i][j + 2]; v.w = acc[i][j + 3];
                    *(float4*)(yp + j) = v;
                }
            } else {
                const int t = row0 + m - RROWS;
                float* op = out + (size_t)t * HID + n0 + tx * 8;
                #pragma unroll
                for (int j = 0; j < 8; j += 4) {
                    const int c = n0 + tx * 8 + j;
                    float4 v;
                    v.x = acc[i][j]     + sdb[c];
                    v.y = acc[i][j + 1] + sdb[c + 1];
                    v.z = acc[i][j + 2] + sdb[c + 2];
                    v.w = acc[i][j + 3] + sdb[c + 3];
                    *(float4*)(op + j) = v;
                }
            }
        }
    }
}

// ---------------- combine: out[t] += w0*y[row0(t)] + w1*y[row1(t)] ----------------
__global__ void combine_kernel(float* __restrict__ out) {
    const size_t i = (size_t)blockIdx.x * 256 + threadIdx.x;
    if (i >= (size_t)T_TOK * HID / 4) return;
    const int t = (int)(i / (HID / 4));
    const int c4 = (int)(i % (HID / 4));
    const int r0 = row_of_d[2 * t];
    const int r1 = row_of_d[2 * t + 1];
    const float w0 = topk_w_d[2 * t];
    const float w1 = topk_w_d[2 * t + 1];
    float4 o = ((const float4*)out)[i];
    const float4 y0 = ((const float4*)y_buf)[(size_t)r0 * (HID / 4) + c4];
    const float4 y1 = ((const float4*)y_buf)[(size_t)r1 * (HID / 4) + c4];
    o.x += w0 * y0.x + w1 * y1.x;
    o.y += w0 * y0.y + w1 * y1.y;
    o.z += w0 * y0.z + w1 * y1.z;
    o.w += w0 * y0.w + w1 * y1.w;
    ((float4*)out)[i] = o;
}

// ---------------- launcher (graph-capturable: fixed grids, no sync/alloc) ----------------
extern "C" void kernel_launch(void* const* d_in, const int* in_sizes, int n_in,
                              void* d_out, int out_size) {
    const float* x   = (const float*)d_in[0];   // hidden_states [B,S,H]
    const float* rw  = (const float*)d_in[1];   // router_w [E,H]
    const float* wg  = (const float*)d_in[2];   // [E,H,I]
    const float* wu  = (const float*)d_in[3];   // [E,H,I]
    const float* wd  = (const float*)d_in[4];   // [E,I,H]
    const float* sgw = (const float*)d_in[5];   // [H,I]
    const float* sgb = (const float*)d_in[6];   // [I]
    const float* suw = (const float*)d_in[7];   // [H,I]
    const float* sub = (const float*)d_in[8];   // [I]
    const float* sdw = (const float*)d_in[9];   // [I,H]
    const float* sdb = (const float*)d_in[10];  // [H]
    float* out = (float*)d_out;

    router_kernel<<<T_TOK, 256>>>(x, rw);
    build_kernel<<<1, 256>>>();
    dim3 gup(MAXTILES, IDIM / 128, 2);
    up_gemm_kernel<<<gup, 256>>>(x, wg, wu, sgw, suw, sgb, sub);
    act_kernel<<<(NROWS * (IDIM / 4) + 255) / 256, 256>>>();
    dim3 gdn(MAXTILES, HID / 128, 1);
    down_gemm_kernel<<<gdn, 256>>>(wd, sdw, sdb, out);
    combine_kernel<<<(T_TOK * (HID / 4) + 255) / 256, 256>>>(out);
}

// round 3
// speedup vs baseline: 1.0006x; 1.0006x over previous
#include <cuda_runtime.h>
#include <math.h>

// ---------------- problem constants ----------------
#define T_TOK 4096       // B*S tokens
#define HID   2048       // hidden size
#define NEXP  8          // experts
#define IDIM  1024       // expert intermediate
#define RROWS 8192       // routed rows = T_TOK * top_k (always exact)
#define SROWS 4096       // shared-expert rows
#define NROWS 12288      // RROWS + SROWS
#define MAXTILES 128     // >= sum ceil(n_e/128) (<=71) + 32 shared tiles

// ---------------- static device scratch (no cudaMalloc allowed) ----------------
__device__ float g_buf[(size_t)NROWS * IDIM];   // gate pre-act, then h = silu(g)*u
__device__ float u_buf[(size_t)NROWS * IDIM];   // up pre-act
__device__ float y_buf[(size_t)RROWS * HID];    // routed expert down-proj outputs
__device__ int   topk_idx_d[T_TOK * 2];
__device__ float topk_w_d[T_TOK * 2];
__device__ int   tok_d[NROWS];                  // row -> token id
__device__ int   row_of_d[T_TOK * 2];           // (token,slot) -> routed row (inverse map)
__device__ int   tile_grp_d[MAXTILES];
__device__ int   tile_row0_d[MAXTILES];
__device__ int   tile_rows_d[MAXTILES];
__device__ int   n_tiles_d;
__device__ int   grp_off_d[NEXP + 1];

// ---------------- router: logits + top-2 (raw logits are combine weights) ----------------
__global__ __launch_bounds__(256) void router_kernel(const float* __restrict__ x,
                                                     const float* __restrict__ rw) {
    __shared__ float sx[HID];
    __shared__ float slog[NEXP];
    const int t = blockIdx.x;
    const float* xr = x + (size_t)t * HID;
    for (int i = threadIdx.x; i < HID / 4; i += 256)
        ((float4*)sx)[i] = ((const float4*)xr)[i];
    __syncthreads();
    const int w = threadIdx.x >> 5, lane = threadIdx.x & 31;  // 8 warps = 8 experts
    const float* re = rw + (size_t)w * HID;
    float s = 0.f;
    for (int k = lane; k < HID; k += 32) s += sx[k] * re[k];
    #pragma unroll
    for (int o = 16; o; o >>= 1) s += __shfl_down_sync(0xffffffffu, s, o);
    if (lane == 0) slog[w] = s;
    __syncthreads();
    if (threadIdx.x == 0) {
        float b = -3.4e38f; int bi = 0;
        #pragma unroll
        for (int e = 0; e < NEXP; e++) if (slog[e] > b) { b = slog[e]; bi = e; }
        float b2 = -3.4e38f; int si = 0;
        #pragma unroll
        for (int e = 0; e < NEXP; e++) if (e != bi && slog[e] > b2) { b2 = slog[e]; si = e; }
        topk_idx_d[2 * t] = bi;      topk_w_d[2 * t] = b;
        topk_idx_d[2 * t + 1] = si;  topk_w_d[2 * t + 1] = b2;
    }
}

// ---------------- deterministic list build: stable compaction per expert ----------------
__global__ void build_kernel() {
    __shared__ int sscan[256];
    __shared__ int sbase, sebase;
    const int tid = threadIdx.x;
    if (tid == 0) { sebase = 0; grp_off_d[0] = 0; }
    __syncthreads();
    for (int e = 0; e < NEXP; e++) {
        if (tid == 0) sbase = 0;
        __syncthreads();
        for (int c = 0; c < T_TOK; c += 256) {
            const int t = c + tid;
            int slot = -1;
            if (topk_idx_d[2 * t] == e) slot = 0;
            else if (topk_idx_d[2 * t + 1] == e) slot = 1;
            const int f = (slot >= 0) ? 1 : 0;
            sscan[tid] = f;
            __syncthreads();
            #pragma unroll
            for (int o = 1; o < 256; o <<= 1) {
                int v = (tid >= o) ? sscan[tid - o] : 0;
                __syncthreads();
                sscan[tid] += v;
                __syncthreads();
            }
            if (f) {
                const int pos = sebase + sbase + sscan[tid] - 1;
                tok_d[pos] = t;
                row_of_d[2 * t + slot] = pos;
            }
            const int tot = sscan[255];
            __syncthreads();
            if (tid == 0) sbase += tot;
            __syncthreads();
        }
        if (tid == 0) { sebase += sbase; grp_off_d[e + 1] = sebase; }
        __syncthreads();
    }
    // shared-expert pseudo-group covers all tokens
    for (int i = tid; i < SROWS; i += 256) tok_d[RROWS + i] = i;
    __syncthreads();
    if (tid == 0) {
        int nt = 0;
        for (int g = 0; g < NEXP; g++) {
            const int r0 = grp_off_d[g], r1 = grp_off_d[g + 1];
            for (int r = r0; r < r1; r += 128) {
                tile_grp_d[nt] = g; tile_row0_d[nt] = r;
                tile_rows_d[nt] = min(128, r1 - r); nt++;
            }
        }
        for (int r = RROWS; r < NROWS; r += 128) {
            tile_grp_d[nt] = NEXP; tile_row0_d[nt] = r; tile_rows_d[nt] = 128; nt++;
        }
        n_tiles_d = nt;
    }
}

// ---------------- up/gate grouped GEMM: C = gather(X) @ B ----------------
// blockIdx.z: 0 -> gate weights into g_buf, 1 -> up weights into u_buf.
__global__ __launch_bounds__(256) void up_gemm_kernel(
    const float* __restrict__ x,
    const float* __restrict__ wg, const float* __restrict__ wu,
    const float* __restrict__ sgw, const float* __restrict__ suw,
    const float* __restrict__ sgb, const float* __restrict__ sub) {
    const int tile = blockIdx.x;
    if (tile >= n_tiles_d) return;
    const int g = tile_grp_d[tile];
    const int row0 = tile_row0_d[tile];
    const int rows = tile_rows_d[tile];
    const int z = blockIdx.z;
    const float* B;
    const float* bias = nullptr;
    if (g < NEXP) B = (z ? wu : wg) + (size_t)g * HID * IDIM;
    else { B = z ? suw : sgw; bias = z ? sub : sgb; }
    float* C = z ? u_buf : g_buf;
    const int n0 = blockIdx.y * 128;

    __shared__ float As[16][128];
    __shared__ float Bs[16][128];

    const int tid = threadIdx.x;
    const int tx = tid & 15, ty = tid >> 4;
    const int am = tid & 127;
    const int ak = (tid >> 7) * 8;
    const int tok = tok_d[row0 + am];           // row0+127 < NROWS always
    const float* aptr = x + (size_t)tok * HID + ak;
    const int bn = (tid & 31) * 4;
    const int bk = tid >> 5;

    float acc[8][8];
    #pragma unroll
    for (int i = 0; i < 8; i++)
        #pragma unroll
        for (int j = 0; j < 8; j++) acc[i][j] = 0.f;

    for (int k0 = 0; k0 < HID; k0 += 16) {
        float4 a0 = *(const float4*)(aptr + k0);
        float4 a1 = *(const float4*)(aptr + k0 + 4);
        As[ak + 0][am] = a0.x; As[ak + 1][am] = a0.y;
        As[ak + 2][am] = a0.z; As[ak + 3][am] = a0.w;
        As[ak + 4][am] = a1.x; As[ak + 5][am] = a1.y;
        As[ak + 6][am] = a1.z; As[ak + 7][am] = a1.w;
        const float* bp = B + (size_t)(k0 + bk) * IDIM + n0 + bn;
        *(float4*)&Bs[bk][bn]     = *(const float4*)bp;
        *(float4*)&Bs[bk + 8][bn] = *(const float4*)(bp + 8 * IDIM);
        __syncthreads();
        #pragma unroll
        for (int k = 0; k < 16; k++) {
            float a[8], b[8];
            *(float4*)(a)     = *(float4*)&As[k][ty * 8];
            *(float4*)(a + 4) = *(float4*)&As[k][ty * 8 + 4];
            *(float4*)(b)     = *(float4*)&Bs[k][tx * 8];
            *(float4*)(b + 4) = *(float4*)&Bs[k][tx * 8 + 4];
            #pragma unroll
            for (int i = 0; i < 8; i++)
                #pragma unroll
                for (int j = 0; j < 8; j++) acc[i][j] += a[i] * b[j];
        }
        __syncthreads();
    }
    #pragma unroll
    for (int i = 0; i < 8; i++) {
        const int m = ty * 8 + i;
        if (m < rows) {
            float* cp = C + (size_t)(row0 + m) * IDIM + n0 + tx * 8;
            #pragma unroll
            for (int j = 0; j < 8; j += 4) {
                float4 v;
                v.x = acc[i][j]; v.y = acc[i][j + 1]; v.z = acc[i][j + 2]; v.w = acc[i][j + 3];
                if (bias) {
                    const int c = n0 + tx * 8 + j;
                    v.x += bias[c]; v.y += bias[c + 1]; v.z += bias[c + 2]; v.w += bias[c + 3];
                }
                *(float4*)(cp + j) = v;
            }
        }
    }
}

// ---------------- h = silu(g) * u, in place into g_buf ----------------
__global__ void act_kernel() {
    const size_t i = (size_t)blockIdx.x * 256 + threadIdx.x;
    if (i >= (size_t)NROWS * IDIM / 4) return;
    float4 gv = ((const float4*)g_buf)[i];
    float4 uv = ((const float4*)u_buf)[i];
    gv.x = gv.x / (1.f + expf(-gv.x)) * uv.x;
    gv.y = gv.y / (1.f + expf(-gv.y)) * uv.y;
    gv.z = gv.z / (1.f + expf(-gv.z)) * uv.z;
    gv.w = gv.w / (1.f + expf(-gv.w)) * uv.w;
    ((float4*)g_buf)[i] = gv;
}

// ---------------- down grouped GEMM: routed -> y_buf, shared -> out (+bias) ----------------
__global__ __launch_bounds__(256) void down_gemm_kernel(
    const float* __restrict__ wd, const float* __restrict__ sdw,
    const float* __restrict__ sdb, float* __restrict__ out) {
    const int tile = blockIdx.x;
    if (tile >= n_tiles_d) return;
    const int g = tile_grp_d[tile];
    const int row0 = tile_row0_d[tile];
    const int rows = tile_rows_d[tile];
    const float* B = (g < NEXP) ? wd + (size_t)g * IDIM * HID : sdw;
    const int n0 = blockIdx.y * 128;

    __shared__ float As[16][128];
    __shared__ float Bs[16][128];

    const int tid = threadIdx.x;
    const int tx = tid & 15, ty = tid >> 4;
    const int am = tid & 127;
    const int ak = (tid >> 7) * 8;
    const float* aptr = g_buf + (size_t)(row0 + am) * IDIM + ak;
    const int bn = (tid & 31) * 4;
    const int bk = tid >> 5;

    float acc[8][8];
    #pragma unroll
    for (int i = 0; i < 8; i++)
        #pragma unroll
        for (int j = 0; j < 8; j++) acc[i][j] = 0.f;

    for (int k0 = 0; k0 < IDIM; k0 += 16) {
        float4 a0 = *(const float4*)(aptr + k0);
        float4 a1 = *(const float4*)(aptr + k0 + 4);
        As[ak + 0][am] = a0.x; As[ak + 1][am] = a0.y;
        As[ak + 2][am] = a0.z; As[ak + 3][am] = a0.w;
        As[ak + 4][am] = a1.x; As[ak + 5][am] = a1.y;
        As[ak + 6][am] = a1.z; As[ak + 7][am] = a1.w;
        const float* bp = B + (size_t)(k0 + bk) * HID + n0 + bn;
        *(float4*)&Bs[bk][bn]     = *(const float4*)bp;
        *(float4*)&Bs[bk + 8][bn] = *(const float4*)(bp + 8 * HID);
        __syncthreads();
        #pragma unroll
        for (int k = 0; k < 16; k++) {
            float a[8], b[8];
            *(float4*)(a)     = *(float4*)&As[k][ty * 8];
            *(float4*)(a + 4) = *(float4*)&As[k][ty * 8 + 4];
            *(float4*)(b)     = *(float4*)&Bs[k][tx * 8];
            *(float4*)(b + 4) = *(float4*)&Bs[k][tx * 8 + 4];
            #pragma unroll
            for (int i = 0; i < 8; i++)
                #pragma unroll
                for (int j = 0; j < 8; j++) acc[i][j] += a[i] * b[j];
        }
        __syncthreads();
    }
    #pragma unroll
    for (int i = 0; i < 8; i++) {
        const int m = ty * 8 + i;
        if (m < rows) {
            if (g < NEXP) {
                float* yp = y_buf + (size_t)(row0 + m) * HID + n0 + tx * 8;
                #pragma unroll
                for (int j = 0; j < 8; j += 4) {
                    float4 v;
                    v.x = acc[i][j]; v.y = acc[i][j + 1]; v.z = acc[i][j + 2]; v.w = acc[i][j + 3];
                    *(float4*)(yp + j) = v;
                }
            } else {
                const int t = row0 + m - RROWS;
                float* op = out + (size_t)t * HID + n0 + tx * 8;
                #pragma unroll
                for (int j = 0; j < 8; j += 4) {
                    const int c = n0 + tx * 8 + j;
                    float4 v;
                    v.x = acc[i][j]     + sdb[c];
                    v.y = acc[i][j + 1] + sdb[c + 1];
                    v.z = acc[i][j + 2] + sdb[c + 2];
                    v.w = acc[i][j + 3] + sdb[c + 3];
                    *(float4*)(op + j) = v;
                }
            }
        }
    }
}

// ---------------- combine: out[t] += w0*y[row0(t)] + w1*y[row1(t)] ----------------
__global__ void combine_kernel(float* __restrict__ out) {
    const size_t i = (size_t)blockIdx.x * 256 + threadIdx.x;
    if (i >= (size_t)T_TOK * HID / 4) return;
    const int t = (int)(i / (HID / 4));
    const int c4 = (int)(i % (HID / 4));
    const int r0 = row_of_d[2 * t];
    const int r1 = row_of_d[2 * t + 1];
    const float w0 = topk_w_d[2 * t];
    const float w1 = topk_w_d[2 * t + 1];
    float4 o = ((const float4*)out)[i];
    const float4 y0 = ((const float4*)y_buf)[(size_t)r0 * (HID / 4) + c4];
    const float4 y1 = ((const float4*)y_buf)[(size_t)r1 * (HID / 4) + c4];
    o.x += w0 * y0.x + w1 * y1.x;
    o.y += w0 * y0.y + w1 * y1.y;
    o.z += w0 * y0.z + w1 * y1.z;
    o.w += w0 * y0.w + w1 * y1.w;
    ((float4*)out)[i] = o;
}

// ---------------- launcher (graph-capturable: fixed grids, no sync/alloc) ----------------
extern "C" void kernel_launch(void* const* d_in, const int* in_sizes, int n_in,
                              void* d_out, int out_size) {
    const float* x   = (const float*)d_in[0];   // hidden_states [B,S,H]
    const float* rw  = (const float*)d_in[1];   // router_w [E,H]
    const float* wg  = (const float*)d_in[2];   // [E,H,I]
    const float* wu  = (const float*)d_in[3];   // [E,H,I]
    const float* wd  = (const float*)d_in[4];   // [E,I,H]
    const float* sgw = (const float*)d_in[5];   // [H,I]
    const float* sgb = (const float*)d_in[6];   // [I]
    const float* suw = (const float*)d_in[7];   // [H,I]
    const float* sub = (const float*)d_in[8];   // [I]
    const float* sdw = (const float*)d_in[9];   // [I,H]
    const float* sdb = (const float*)d_in[10];  // [H]
    float* out = (float*)d_out;

    router_kernel<<<T_TOK, 256>>>(x, rw);
    build_kernel<<<1, 256>>>();
    dim3 gup(MAXTILES, IDIM / 128, 2);
    up_gemm_kernel<<<gup, 256>>>(x, wg, wu, sgw, suw, sgb, sub);
    act_kernel<<<(NROWS * (IDIM / 4) + 255) / 256, 256>>>();
    dim3 gdn(MAXTILES, HID / 128, 1);
    down_gemm_kernel<<<gdn, 256>>>(wd, sdw, sdb, out);
    combine_kernel<<<(T_TOK * (HID / 4) + 255) / 256, 256>>>(out);
}